// round 5
// baseline (speedup 1.0000x reference)
#include <cuda_runtime.h>
#include <cuda_fp16.h>
#include <math.h>
#include <stdint.h>

// Problem constants
#define BATCH   32
#define CHAN    256
#define HH      56
#define WW      56
#define HWHW    3136
#define NWEIGHT (CHAN*CHAN*9)
#define KDIM    2304
#define MDIM    (BATCH*HWHW)            // 100352

// Padded NHWC activation layout
#define PADW    58
#define XPLANE  (PADW*PADW*CHAN)        // 861184
#define NXPAD   (BATCH*XPLANE)          // 27557888 halves per pass

// GEMM tiling
#define BM 128
#define BN 256
#define BK 64
#define NCHUNK 72                       // 2 passes * 9 taps * 4 ci-quarters
#define STAGES 3
#define AST 72                          // 64 + 8 pad halves (144B rows, LDSM conflict-free)
#define BST 264                         // 256 + 8 pad halves (528B rows, conflict-free)
#define A_BYTES (BM*AST*2)              // 18432
#define B_BYTES (BK*BST*2)              // 33792
#define STAGE_B (A_BYTES + B_BYTES)     // 52224
#define SMEM_REQ (STAGES*STAGE_B + 2048)

// ---------------- device scratch ----------------
__device__ __half g_xpad[2*NXPAD];          // padded NHWC hi/lo (~110 MB), borders stay 0
__device__ __half g_wmat[9*CHAN*CHAN];      // weights*15 as [tap][ci][oc]
__device__ float  g_scale[CHAN];
__device__ float  g_bias[CHAN];
__device__ float  g_T;

__device__ __forceinline__ uint32_t smem_u32(const void* p) {
    return (uint32_t)__cvta_generic_to_shared(p);
}

// ---------------- kernel 1: max |tanh(w)| (single block) --------------------
__global__ __launch_bounds__(1024)
void k_max(const float* __restrict__ w) {
    __shared__ float s[1024];
    float m = 0.0f;
    for (int i = threadIdx.x; i < NWEIGHT; i += 1024) {
        float t = (float)tanh((double)w[i]);
        m = fmaxf(m, fabsf(t));
    }
    s[threadIdx.x] = m;
    __syncthreads();
    for (int o = 512; o > 0; o >>= 1) {
        if (threadIdx.x < o) s[threadIdx.x] = fmaxf(s[threadIdx.x], s[threadIdx.x+o]);
        __syncthreads();
    }
    if (threadIdx.x == 0) g_T = s[0];
}

// ---------------- kernel 2: weight quantize [tap][ci][oc] + BN fold ---------
__global__ void k_prep_w(const float* __restrict__ w,
                         const float* __restrict__ gamma, const float* __restrict__ beta,
                         const float* __restrict__ mean,  const float* __restrict__ var) {
    int e = blockIdx.x*256 + threadIdx.x;      // grid KDIM x 256 == NWEIGHT
    float T = g_T;
    float t  = (float)tanh((double)w[e]);
    float tq = __fdiv_rn(t, 2.0f*T) + 0.5f;
    float r  = rintf(tq * 15.0f);              // half-even, matches jnp.round
    int oc = e / KDIM;
    int rr = e - oc*KDIM;
    int ci = rr / 9;
    int tap = rr - ci*9;
    g_wmat[(tap*CHAN + ci)*CHAN + oc] = __float2half(2.0f*r - 15.0f);

    if (blockIdx.x == 0) {
        int c = threadIdx.x;
        float inv = __fdiv_rn(gamma[c], __fsqrt_rn(var[c] + 1e-5f));
        g_scale[c] = __fdiv_rn(inv, 15.0f);
        g_bias[c]  = fmaf(-mean[c], inv, beta[c]);
    }
}

// ---------------- kernel 3: NCHW fp32 -> padded NHWC fp16 hi/lo -------------
__global__ __launch_bounds__(128)
void k_convert(const float* __restrict__ x) {
    __shared__ __half sh[2][56][136];
    int bid = blockIdx.x;
    int cihalf = bid & 1;
    int bh = bid >> 1;
    int h = bh % HH;
    int b = bh / HH;
    int t = threadIdx.x;

    const float* xp = x + ((size_t)(b*CHAN + cihalf*128)*HH + h)*WW;
    #pragma unroll
    for (int i = 0; i < 14; i++) {
        int f = i*128 + t;
        int ci = f / 14;
        int c4 = f - ci*14;
        float4 v = *reinterpret_cast<const float4*>(xp + (size_t)ci*HWHW + c4*4);
        int w4 = c4*4;
        float vv[4] = {v.x, v.y, v.z, v.w};
        #pragma unroll
        for (int j = 0; j < 4; j++) {
            __half hh = __float2half(vv[j]);
            sh[0][w4+j][ci] = hh;
            sh[1][w4+j][ci] = __float2half(vv[j] - __half2float(hh));
        }
    }
    __syncthreads();
    int obase = b*XPLANE + ((h+1)*PADW + 1)*CHAN + cihalf*128;
    #pragma unroll
    for (int i = 0; i < 7; i++) {
        int u = i*128 + t;
        int w = u >> 4;
        int c16 = (u & 15)*8;
        uint4 dhi = *reinterpret_cast<const uint4*>(&sh[0][w][c16]);
        uint4 dlo = *reinterpret_cast<const uint4*>(&sh[1][w][c16]);
        int o = obase + w*CHAN + c16;
        *reinterpret_cast<uint4*>(&g_xpad[o])         = dhi;
        *reinterpret_cast<uint4*>(&g_xpad[NXPAD + o]) = dlo;
    }
}

// ---------------- kernel 4: implicit GEMM, cp.async + mma.sync 64x64 --------
__global__ __launch_bounds__(256, 1)
void k_conv(const float* __restrict__ alpha_p, float* __restrict__ out) {
    extern __shared__ char smem[];
    float* s_scale = (float*)(smem + STAGES*STAGE_B);
    float* s_bias  = s_scale + CHAN;

    int tid  = threadIdx.x;
    int warp = tid >> 5, lane = tid & 31;
    int wm = warp >> 2, wn = warp & 3;          // 2x4 warp grid; warp tile 64x64

    if (tid < CHAN) { s_scale[tid] = g_scale[tid]; s_bias[tid] = g_bias[tid]; }

    int m0 = blockIdx.x * BM;

    // A loader: thread covers row (tid>>1), 4 x 16B units at half-offset (tid&1)*32
    int arow = tid >> 1;
    int gm  = m0 + arow;
    int b   = gm / HWHW;  int rem = gm - b*HWHW;
    int h   = rem / WW;   int w   = rem - h*WW;
    const __half* abase = g_xpad + b*XPLANE + (h*PADW + w)*CHAN + (tid & 1)*32;
    uint32_t adst0 = smem_u32(smem) + (uint32_t)(arow*AST + (tid & 1)*32)*2;

    // B loader: 8 units: rows (tid>>5)+8j, unit col (tid&31)
    const __half* wbase = g_wmat + (tid >> 5)*CHAN + (tid & 31)*8;
    uint32_t bdst0 = smem_u32(smem) + (uint32_t)A_BYTES +
                     (uint32_t)((tid >> 5)*BST + (tid & 31)*8)*2;

    float acc[4][8][4];
    #pragma unroll
    for (int mf = 0; mf < 4; mf++)
        #pragma unroll
        for (int nf = 0; nf < 8; nf++)
            #pragma unroll
            for (int j = 0; j < 4; j++) acc[mf][nf][j] = 0.0f;

    auto fill = [&](int c) {
        int pass = (c >= 36) ? 1 : 0;
        int cc   = c - pass*36;
        int tap  = cc >> 2;
        int cq   = cc & 3;
        int kh = tap / 3, kw = tap - kh*3;
        int st = c % STAGES;
        const __half* asrc = abase + (long)pass*NXPAD + (kh*PADW + kw)*CHAN + cq*64;
        uint32_t ad = adst0 + st*STAGE_B;
        #pragma unroll
        for (int i = 0; i < 4; i++)
            asm volatile("cp.async.cg.shared.global [%0], [%1], 16;"
                :: "r"(ad + i*16), "l"(asrc + i*8));
        const __half* bsrc = wbase + (tap*CHAN + cq*64)*CHAN;
        uint32_t bd = bdst0 + st*STAGE_B;
        #pragma unroll
        for (int j = 0; j < 8; j++)
            asm volatile("cp.async.cg.shared.global [%0], [%1], 16;"
                :: "r"(bd + (uint32_t)(j*8*BST)*2), "l"(bsrc + j*8*CHAN));
        asm volatile("cp.async.commit_group;");
    };

    fill(0); fill(1);

    for (int c = 0; c < NCHUNK; c++) {
        asm volatile("cp.async.wait_group %0;" :: "n"(1));
        __syncthreads();
        if (c + 2 < NCHUNK) fill(c + 2);
        else asm volatile("cp.async.commit_group;");

        int st = c % STAGES;
        const __half* Ab = (const __half*)(smem + st*STAGE_B);
        const __half* Bb = (const __half*)(smem + st*STAGE_B + A_BYTES);
        #pragma unroll
        for (int kk = 0; kk < 4; kk++) {
            uint32_t afr[4][4];
            uint32_t bfr[8][2];
            #pragma unroll
            for (int mf = 0; mf < 4; mf++) {
                int row = wm*64 + mf*16 + (lane & 15);
                int col = kk*16 + ((lane >> 4) << 3);
                uint32_t addr = smem_u32(&Ab[row*AST + col]);
                asm volatile("ldmatrix.sync.aligned.m8n8.x4.shared.b16 {%0,%1,%2,%3},[%4];"
                    : "=r"(afr[mf][0]), "=r"(afr[mf][1]), "=r"(afr[mf][2]), "=r"(afr[mf][3])
                    : "r"(addr));
            }
            #pragma unroll
            for (int bg = 0; bg < 4; bg++) {
                int row = kk*16 + (lane & 15);
                int col = wn*64 + bg*16 + ((lane >> 4) << 3);
                uint32_t addr = smem_u32(&Bb[row*BST + col]);
                asm volatile("ldmatrix.sync.aligned.m8n8.x4.trans.shared.b16 {%0,%1,%2,%3},[%4];"
                    : "=r"(bfr[bg*2][0]), "=r"(bfr[bg*2][1]),
                      "=r"(bfr[bg*2+1][0]), "=r"(bfr[bg*2+1][1])
                    : "r"(addr));
            }
            #pragma unroll
            for (int mf = 0; mf < 4; mf++)
                #pragma unroll
                for (int nf = 0; nf < 8; nf++)
                    asm volatile(
                        "mma.sync.aligned.m16n8k16.row.col.f32.f16.f16.f32 "
                        "{%0,%1,%2,%3},{%4,%5,%6,%7},{%8,%9},{%0,%1,%2,%3};"
                        : "+f"(acc[mf][nf][0]), "+f"(acc[mf][nf][1]),
                          "+f"(acc[mf][nf][2]), "+f"(acc[mf][nf][3])
                        : "r"(afr[mf][0]), "r"(afr[mf][1]), "r"(afr[mf][2]), "r"(afr[mf][3]),
                          "r"(bfr[nf][0]), "r"(bfr[nf][1]));
        }
    }

    // ---- epilogue: BN + PACT quantization ----
    float aval = alpha_p[0];
    float back = __fdiv_rn(aval, 15.0f);
    #pragma unroll
    for (int mf = 0; mf < 4; mf++) {
        #pragma unroll
        for (int jh = 0; jh < 2; jh++) {
            int rm  = m0 + wm*64 + mf*16 + (lane >> 2) + jh*8;
            int b2  = rm / HWHW;
            int hw2 = rm - b2*HWHW;
            float* obase = out + b2*CHAN*HWHW + hw2;
            #pragma unroll
            for (int nf = 0; nf < 8; nf++) {
                #pragma unroll
                for (int jl = 0; jl < 2; jl++) {
                    int j  = jh*2 + jl;
                    int oc = wn*64 + nf*8 + ((lane & 3) << 1) + jl;
                    float y = fmaf(acc[mf][nf][j], s_scale[oc], s_bias[oc]);
                    y = fminf(fmaxf(y, 0.0f), aval);
                    float q = rintf(__fdiv_rn(y * 15.0f, aval)) * back;
                    obase[oc * HWHW] = q;
                }
            }
        }
    }
}

// ---------------- launch ----------------------------------------------------
extern "C" void kernel_launch(void* const* d_in, const int* in_sizes, int n_in,
                              void* d_out, int out_size) {
    const float* x     = (const float*)d_in[0];
    const float* w     = (const float*)d_in[1];
    const float* gamma = (const float*)d_in[2];
    const float* beta  = (const float*)d_in[3];
    const float* mean  = (const float*)d_in[4];
    const float* var   = (const float*)d_in[5];
    const float* alpha = (const float*)d_in[6];
    float* out = (float*)d_out;

    static int smem_set = 0;
    if (!smem_set) {
        cudaFuncSetAttribute(k_conv, cudaFuncAttributeMaxDynamicSharedMemorySize, SMEM_REQ);
        smem_set = 1;
    }

    k_max<<<1, 1024>>>(w);
    k_prep_w<<<KDIM, 256>>>(w, gamma, beta, mean, var);
    k_convert<<<BATCH*HH*2, 128>>>(x);
    k_conv<<<MDIM/BM, 256, SMEM_REQ>>>(alpha, out);
}

// round 9
// speedup vs baseline: 3.5038x; 3.5038x over previous
#include <cuda_runtime.h>
#include <cuda_fp16.h>
#include <math.h>
#include <stdint.h>

// Problem constants
#define BATCH   32
#define CHAN    256
#define HH      56
#define WW      56
#define HWHW    3136
#define NWEIGHT (CHAN*CHAN*9)
#define KDIM    2304
#define MDIM    (BATCH*HWHW)            // 100352

// Padded NHWC activation layout
#define PADW    58
#define XPLANE  (PADW*PADW*CHAN)        // 861184
#define NXPAD   (BATCH*XPLANE)          // 27557888 halves per pass

// GEMM tiling
#define BM 128
#define BN 256
#define BK 64
#define NCHUNK 72                       // 2 passes * 9 taps * 4 ci-quarters
#define STAGES 3
#define AST 72                          // 64 + 8 pad halves (144B rows, LDSM conflict-free)
#define BST 264                         // 256 + 8 pad halves (528B rows, conflict-free)
#define A_BYTES (BM*AST*2)              // 18432
#define B_BYTES (BK*BST*2)              // 33792
#define STAGE_B (A_BYTES + B_BYTES)     // 52224
#define SMEM_REQ (STAGES*STAGE_B + 2048)

// ---------------- device scratch ----------------
__device__ __half g_xpad[2*NXPAD];          // padded NHWC hi/lo (~110 MB), borders stay 0
__device__ __half g_wmat[9*CHAN*CHAN];      // weights*15 as [tap][ci][oc]
__device__ float  g_scale[CHAN];
__device__ float  g_bias[CHAN];
__device__ unsigned g_Tbits;                // max |tanh(w)| as positive-float bits

__device__ __forceinline__ uint32_t smem_u32(const void* p) {
    return (uint32_t)__cvta_generic_to_shared(p);
}

// ---------------- kernel 1: max |tanh(w)| (parallel + atomicMax) ------------
__global__ __launch_bounds__(256)
void k_max(const float* __restrict__ w) {
    __shared__ float s[256];
    float m = 0.0f;
    for (int i = blockIdx.x*256 + threadIdx.x; i < NWEIGHT; i += 256*256) {
        float t = (float)tanh((double)w[i]);
        m = fmaxf(m, fabsf(t));
    }
    s[threadIdx.x] = m;
    __syncthreads();
    for (int o = 128; o > 0; o >>= 1) {
        if (threadIdx.x < o) s[threadIdx.x] = fmaxf(s[threadIdx.x], s[threadIdx.x+o]);
        __syncthreads();
    }
    // positive floats: bit pattern is order-isomorphic -> atomicMax on uint is exact
    if (threadIdx.x == 0) atomicMax(&g_Tbits, __float_as_uint(s[0]));
}

// ---------------- kernel 2: weight quantize [tap][ci][oc] + BN fold ---------
__global__ void k_prep_w(const float* __restrict__ w,
                         const float* __restrict__ gamma, const float* __restrict__ beta,
                         const float* __restrict__ mean,  const float* __restrict__ var) {
    int e = blockIdx.x*256 + threadIdx.x;      // grid KDIM x 256 == NWEIGHT
    float T = __uint_as_float(g_Tbits);
    float t  = (float)tanh((double)w[e]);
    float tq = __fdiv_rn(t, 2.0f*T) + 0.5f;
    float r  = rintf(tq * 15.0f);              // half-even, matches jnp.round
    int oc = e / KDIM;
    int rr = e - oc*KDIM;
    int ci = rr / 9;
    int tap = rr - ci*9;
    g_wmat[(tap*CHAN + ci)*CHAN + oc] = __float2half(2.0f*r - 15.0f);

    if (blockIdx.x == 0) {
        int c = threadIdx.x;
        float inv = __fdiv_rn(gamma[c], __fsqrt_rn(var[c] + 1e-5f));
        g_scale[c] = __fdiv_rn(inv, 15.0f);
        g_bias[c]  = fmaf(-mean[c], inv, beta[c]);
    }
}

// ---------------- kernel 3: NCHW fp32 -> padded NHWC fp16 hi/lo -------------
__global__ __launch_bounds__(128)
void k_convert(const float* __restrict__ x) {
    __shared__ __half sh[2][56][136];
    int bid = blockIdx.x;
    int cihalf = bid & 1;
    int bh = bid >> 1;
    int h = bh % HH;
    int b = bh / HH;
    int t = threadIdx.x;

    const float* xp = x + ((size_t)(b*CHAN + cihalf*128)*HH + h)*WW;
    #pragma unroll
    for (int i = 0; i < 14; i++) {
        int f = i*128 + t;
        int ci = f / 14;
        int c4 = f - ci*14;
        float4 v = *reinterpret_cast<const float4*>(xp + (size_t)ci*HWHW + c4*4);
        int w4 = c4*4;
        float vv[4] = {v.x, v.y, v.z, v.w};
        #pragma unroll
        for (int j = 0; j < 4; j++) {
            __half hh = __float2half(vv[j]);
            sh[0][w4+j][ci] = hh;
            sh[1][w4+j][ci] = __float2half(vv[j] - __half2float(hh));
        }
    }
    __syncthreads();
    int obase = b*XPLANE + ((h+1)*PADW + 1)*CHAN + cihalf*128;
    #pragma unroll
    for (int i = 0; i < 7; i++) {
        int u = i*128 + t;
        int w = u >> 4;
        int c16 = (u & 15)*8;
        uint4 dhi = *reinterpret_cast<const uint4*>(&sh[0][w][c16]);
        uint4 dlo = *reinterpret_cast<const uint4*>(&sh[1][w][c16]);
        int o = obase + w*CHAN + c16;
        *reinterpret_cast<uint4*>(&g_xpad[o])         = dhi;
        *reinterpret_cast<uint4*>(&g_xpad[NXPAD + o]) = dlo;
    }
}

// ---------------- kernel 4: implicit GEMM, cp.async + mma.sync 64x64 --------
__device__ __forceinline__ void load_afrag(const __half* Ab, int wm, int lane, int kk,
                                           uint32_t afr[4][4]) {
    #pragma unroll
    for (int mf = 0; mf < 4; mf++) {
        int row = wm*64 + mf*16 + (lane & 15);
        int col = kk*16 + ((lane >> 4) << 3);
        uint32_t addr = smem_u32(&Ab[row*AST + col]);
        asm volatile("ldmatrix.sync.aligned.m8n8.x4.shared.b16 {%0,%1,%2,%3},[%4];"
            : "=r"(afr[mf][0]), "=r"(afr[mf][1]), "=r"(afr[mf][2]), "=r"(afr[mf][3])
            : "r"(addr));
    }
}

__device__ __forceinline__ void load_bfrag(const __half* Bb, int wn, int lane, int kk,
                                           uint32_t bfr[8][2]) {
    #pragma unroll
    for (int bg = 0; bg < 4; bg++) {
        int row = kk*16 + (lane & 15);
        int col = wn*64 + bg*16 + ((lane >> 4) << 3);
        uint32_t addr = smem_u32(&Bb[row*BST + col]);
        asm volatile("ldmatrix.sync.aligned.m8n8.x4.trans.shared.b16 {%0,%1,%2,%3},[%4];"
            : "=r"(bfr[bg*2][0]), "=r"(bfr[bg*2][1]),
              "=r"(bfr[bg*2+1][0]), "=r"(bfr[bg*2+1][1])
            : "r"(addr));
    }
}

__global__ __launch_bounds__(256, 1)
void k_conv(const float* __restrict__ alpha_p, float* __restrict__ out) {
    extern __shared__ char smem[];
    float* s_scale = (float*)(smem + STAGES*STAGE_B);
    float* s_bias  = s_scale + CHAN;

    int tid  = threadIdx.x;
    int warp = tid >> 5, lane = tid & 31;
    int wm = warp >> 2, wn = warp & 3;          // 2x4 warp grid; warp tile 64x64

    if (tid < CHAN) { s_scale[tid] = g_scale[tid]; s_bias[tid] = g_bias[tid]; }

    int m0 = blockIdx.x * BM;

    // A loader: thread covers row (tid>>1), 4 x 16B units at half-offset (tid&1)*32
    int arow = tid >> 1;
    int gm  = m0 + arow;
    int b   = gm / HWHW;  int rem = gm - b*HWHW;
    int h   = rem / WW;   int w   = rem - h*WW;
    const __half* abase = g_xpad + b*XPLANE + (h*PADW + w)*CHAN + (tid & 1)*32;
    uint32_t adst0 = smem_u32(smem) + (uint32_t)(arow*AST + (tid & 1)*32)*2;

    // B loader: 8 units: rows (tid>>5)+8j, unit col (tid&31)
    const __half* wbase = g_wmat + (tid >> 5)*CHAN + (tid & 31)*8;
    uint32_t bdst0 = smem_u32(smem) + (uint32_t)A_BYTES +
                     (uint32_t)((tid >> 5)*BST + (tid & 31)*8)*2;

    float acc[4][8][4];
    #pragma unroll
    for (int mf = 0; mf < 4; mf++)
        #pragma unroll
        for (int nf = 0; nf < 8; nf++)
            #pragma unroll
            for (int j = 0; j < 4; j++) acc[mf][nf][j] = 0.0f;

    auto fill = [&](int c) {
        int pass = (c >= 36) ? 1 : 0;
        int cc   = c - pass*36;
        int tap  = cc >> 2;
        int cq   = cc & 3;
        int kh = tap / 3, kw = tap - kh*3;
        int st = c % STAGES;
        const __half* asrc = abase + (long)pass*NXPAD + (kh*PADW + kw)*CHAN + cq*64;
        uint32_t ad = adst0 + st*STAGE_B;
        #pragma unroll
        for (int i = 0; i < 4; i++)
            asm volatile("cp.async.cg.shared.global [%0], [%1], 16;"
                :: "r"(ad + i*16), "l"(asrc + i*8));
        const __half* bsrc = wbase + (tap*CHAN + cq*64)*CHAN;
        uint32_t bd = bdst0 + st*STAGE_B;
        #pragma unroll
        for (int j = 0; j < 8; j++)
            asm volatile("cp.async.cg.shared.global [%0], [%1], 16;"
                :: "r"(bd + (uint32_t)(j*8*BST)*2), "l"(bsrc + j*8*CHAN));
        asm volatile("cp.async.commit_group;");
    };

    fill(0); fill(1);

    uint32_t afr[2][4][4];
    uint32_t bfr[2][8][2];

    for (int c = 0; c < NCHUNK; c++) {
        asm volatile("cp.async.wait_group %0;" :: "n"(1));
        __syncthreads();
        if (c + 2 < NCHUNK) fill(c + 2);
        else asm volatile("cp.async.commit_group;");

        int st = c % STAGES;
        const __half* Ab = (const __half*)(smem + st*STAGE_B);
        const __half* Bb = (const __half*)(smem + st*STAGE_B + A_BYTES);

        // prime kk=0 fragments
        load_afrag(Ab, wm, lane, 0, afr[0]);
        load_bfrag(Bb, wn, lane, 0, bfr[0]);

        #pragma unroll
        for (int kk = 0; kk < 4; kk++) {
            int cur = kk & 1, nxt = cur ^ 1;
            if (kk < 3) {                       // prefetch next slice while mma runs
                load_afrag(Ab, wm, lane, kk+1, afr[nxt]);
                load_bfrag(Bb, wn, lane, kk+1, bfr[nxt]);
            }
            #pragma unroll
            for (int mf = 0; mf < 4; mf++)
                #pragma unroll
                for (int nf = 0; nf < 8; nf++)
                    asm volatile(
                        "mma.sync.aligned.m16n8k16.row.col.f32.f16.f16.f32 "
                        "{%0,%1,%2,%3},{%4,%5,%6,%7},{%8,%9},{%0,%1,%2,%3};"
                        : "+f"(acc[mf][nf][0]), "+f"(acc[mf][nf][1]),
                          "+f"(acc[mf][nf][2]), "+f"(acc[mf][nf][3])
                        : "r"(afr[cur][mf][0]), "r"(afr[cur][mf][1]),
                          "r"(afr[cur][mf][2]), "r"(afr[cur][mf][3]),
                          "r"(bfr[cur][nf][0]), "r"(bfr[cur][nf][1]));
        }
    }

    // ---- epilogue: BN + PACT quantization ----
    float aval = alpha_p[0];
    float back = __fdiv_rn(aval, 15.0f);
    #pragma unroll
    for (int mf = 0; mf < 4; mf++) {
        #pragma unroll
        for (int jh = 0; jh < 2; jh++) {
            int rm  = m0 + wm*64 + mf*16 + (lane >> 2) + jh*8;
            int b2  = rm / HWHW;
            int hw2 = rm - b2*HWHW;
            float* obase = out + b2*CHAN*HWHW + hw2;
            #pragma unroll
            for (int nf = 0; nf < 8; nf++) {
                #pragma unroll
                for (int jl = 0; jl < 2; jl++) {
                    int j  = jh*2 + jl;
                    int oc = wn*64 + nf*8 + ((lane & 3) << 1) + jl;
                    float y = fmaf(acc[mf][nf][j], s_scale[oc], s_bias[oc]);
                    y = fminf(fmaxf(y, 0.0f), aval);
                    float q = rintf(__fdiv_rn(y * 15.0f, aval)) * back;
                    obase[oc * HWHW] = q;
                }
            }
        }
    }
}

// ---------------- launch ----------------------------------------------------
extern "C" void kernel_launch(void* const* d_in, const int* in_sizes, int n_in,
                              void* d_out, int out_size) {
    const float* x     = (const float*)d_in[0];
    const float* w     = (const float*)d_in[1];
    const float* gamma = (const float*)d_in[2];
    const float* beta  = (const float*)d_in[3];
    const float* mean  = (const float*)d_in[4];
    const float* var   = (const float*)d_in[5];
    const float* alpha = (const float*)d_in[6];
    float* out = (float*)d_out;

    static int init_done = 0;
    static void* tbits_ptr = 0;
    if (!init_done) {
        cudaFuncSetAttribute(k_conv, cudaFuncAttributeMaxDynamicSharedMemorySize, SMEM_REQ);
        cudaGetSymbolAddress(&tbits_ptr, g_Tbits);
        init_done = 1;
    }

    cudaMemsetAsync(tbits_ptr, 0, 4);          // re-zero the atomic-max cell
    k_max<<<256, 256>>>(w);
    k_prep_w<<<KDIM, 256>>>(w, gamma, beta, mean, var);
    k_convert<<<BATCH*HH*2, 128>>>(x);
    k_conv<<<MDIM/BM, 256, SMEM_REQ>>>(alpha, out);
}

// round 10
// speedup vs baseline: 3.7224x; 1.0624x over previous
#include <cuda_runtime.h>
#include <cuda_fp16.h>
#include <math.h>
#include <stdint.h>

// Problem constants
#define BATCH   32
#define CHAN    256
#define HH      56
#define WW      56
#define HWHW    3136
#define NWEIGHT (CHAN*CHAN*9)
#define KDIM    2304
#define MDIM    (BATCH*HWHW)            // 100352

// Padded NHWC activation layout
#define PADW    58
#define XPLANE  (PADW*PADW*CHAN)        // 861184
#define NXPAD   (BATCH*XPLANE)          // 27557888 halves per pass

// GEMM tiling
#define BM 128
#define BN 256
#define BK 64
#define NCHUNK 72                       // 2 passes * 9 taps * 4 ci-quarters
#define STAGES 3
#define AST 72                          // 64 + 8 pad halves (144B rows, LDSM conflict-free)
#define BST 264                         // 256 + 8 pad halves (528B rows, conflict-free)
#define A_BYTES (BM*AST*2)              // 18432
#define B_BYTES (BK*BST*2)              // 33792
#define STAGE_B (A_BYTES + B_BYTES)     // 52224
#define SMEM_REQ (STAGES*STAGE_B + 2048)

// ---------------- device scratch ----------------
__device__ __half g_xpad[2*NXPAD];          // padded NHWC hi/lo (~110 MB), borders stay 0
__device__ __half g_wmat[9*CHAN*CHAN];      // weights*15 as [tap][ci][oc]
__device__ float  g_scale[CHAN];
__device__ float  g_bias[CHAN];
__device__ unsigned g_Tbits;                // max |tanh(w)| as positive-float bits

__device__ __forceinline__ uint32_t smem_u32(const void* p) {
    return (uint32_t)__cvta_generic_to_shared(p);
}

// ---------------- kernel 1: max |tanh(w)| (parallel + atomicMax) ------------
__global__ __launch_bounds__(256)
void k_max(const float* __restrict__ w) {
    __shared__ float s[256];
    float m = 0.0f;
    for (int i = blockIdx.x*256 + threadIdx.x; i < NWEIGHT; i += 256*256) {
        float t = (float)tanh((double)w[i]);
        m = fmaxf(m, fabsf(t));
    }
    s[threadIdx.x] = m;
    __syncthreads();
    for (int o = 128; o > 0; o >>= 1) {
        if (threadIdx.x < o) s[threadIdx.x] = fmaxf(s[threadIdx.x], s[threadIdx.x+o]);
        __syncthreads();
    }
    // positive floats: bit pattern is order-isomorphic -> atomicMax on uint is exact
    if (threadIdx.x == 0) atomicMax(&g_Tbits, __float_as_uint(s[0]));
}

// ---------------- kernel 2: weight quantize [tap][ci][oc] + BN fold ---------
__global__ void k_prep_w(const float* __restrict__ w,
                         const float* __restrict__ gamma, const float* __restrict__ beta,
                         const float* __restrict__ mean,  const float* __restrict__ var) {
    int e = blockIdx.x*256 + threadIdx.x;      // grid KDIM x 256 == NWEIGHT
    float T = __uint_as_float(g_Tbits);
    float t  = (float)tanh((double)w[e]);
    float tq = __fdiv_rn(t, 2.0f*T) + 0.5f;
    float r  = rintf(tq * 15.0f);              // half-even, matches jnp.round
    int oc = e / KDIM;
    int rr = e - oc*KDIM;
    int ci = rr / 9;
    int tap = rr - ci*9;
    g_wmat[(tap*CHAN + ci)*CHAN + oc] = __float2half(2.0f*r - 15.0f);

    if (blockIdx.x == 0) {
        int c = threadIdx.x;
        float inv = __fdiv_rn(gamma[c], __fsqrt_rn(var[c] + 1e-5f));
        g_scale[c] = __fdiv_rn(inv, 15.0f);
        g_bias[c]  = fmaf(-mean[c], inv, beta[c]);
    }
}

// ---------------- kernel 3: NCHW fp32 -> padded NHWC fp16 hi/lo -------------
__global__ __launch_bounds__(128)
void k_convert(const float* __restrict__ x) {
    __shared__ __half sh[2][56][136];
    int bid = blockIdx.x;
    int cihalf = bid & 1;
    int bh = bid >> 1;
    int h = bh % HH;
    int b = bh / HH;
    int t = threadIdx.x;

    const float* xp = x + ((size_t)(b*CHAN + cihalf*128)*HH + h)*WW;
    #pragma unroll
    for (int i = 0; i < 14; i++) {
        int f = i*128 + t;
        int ci = f / 14;
        int c4 = f - ci*14;
        float4 v = *reinterpret_cast<const float4*>(xp + (size_t)ci*HWHW + c4*4);
        int w4 = c4*4;
        float vv[4] = {v.x, v.y, v.z, v.w};
        #pragma unroll
        for (int j = 0; j < 4; j++) {
            __half hh = __float2half(vv[j]);
            sh[0][w4+j][ci] = hh;
            sh[1][w4+j][ci] = __float2half(vv[j] - __half2float(hh));
        }
    }
    __syncthreads();
    int obase = b*XPLANE + ((h+1)*PADW + 1)*CHAN + cihalf*128;
    #pragma unroll
    for (int i = 0; i < 7; i++) {
        int u = i*128 + t;
        int w = u >> 4;
        int c16 = (u & 15)*8;
        uint4 dhi = *reinterpret_cast<const uint4*>(&sh[0][w][c16]);
        uint4 dlo = *reinterpret_cast<const uint4*>(&sh[1][w][c16]);
        int o = obase + w*CHAN + c16;
        *reinterpret_cast<uint4*>(&g_xpad[o])         = dhi;
        *reinterpret_cast<uint4*>(&g_xpad[NXPAD + o]) = dlo;
    }
}

// ---------------- kernel 4: implicit GEMM, 512 thr, 16 warps, 64x32 tiles ---
__global__ __launch_bounds__(512, 1)
void k_conv(const float* __restrict__ alpha_p, float* __restrict__ out) {
    extern __shared__ char smem[];
    float* s_scale = (float*)(smem + STAGES*STAGE_B);
    float* s_bias  = s_scale + CHAN;

    int tid  = threadIdx.x;
    int warp = tid >> 5, lane = tid & 31;
    int wm = warp >> 3, wn = warp & 7;          // 2x8 warp grid; warp tile 64x32

    if (tid < CHAN) { s_scale[tid] = g_scale[tid]; s_bias[tid] = g_bias[tid]; }

    int m0 = blockIdx.x * BM;

    // A loader: row = tid>>2 (0..127), 2 x 16B units at (tid&3)*16 halves
    int arow = tid >> 2;
    int auc  = tid & 3;
    int gm  = m0 + arow;
    int b   = gm / HWHW;  int rem = gm - b*HWHW;
    int h   = rem / WW;   int w   = rem - h*WW;
    const __half* abase = g_xpad + b*XPLANE + (h*PADW + w)*CHAN + auc*16;
    uint32_t adst0 = smem_u32(smem) + (uint32_t)(arow*AST + auc*16)*2;

    // B loader: 4 units: rows (tid>>5)+16j, unit col (tid&31)
    const __half* wbase = g_wmat + (tid >> 5)*CHAN + (tid & 31)*8;
    uint32_t bdst0 = smem_u32(smem) + (uint32_t)A_BYTES +
                     (uint32_t)((tid >> 5)*BST + (tid & 31)*8)*2;

    float acc[4][4][4];
    #pragma unroll
    for (int mf = 0; mf < 4; mf++)
        #pragma unroll
        for (int nf = 0; nf < 4; nf++)
            #pragma unroll
            for (int j = 0; j < 4; j++) acc[mf][nf][j] = 0.0f;

    auto fill = [&](int c) {
        int pass = (c >= 36) ? 1 : 0;
        int cc   = c - pass*36;
        int tap  = cc >> 2;
        int cq   = cc & 3;
        int kh = tap / 3, kw = tap - kh*3;
        int st = c % STAGES;
        const __half* asrc = abase + (long)pass*NXPAD + (kh*PADW + kw)*CHAN + cq*64;
        uint32_t ad = adst0 + st*STAGE_B;
        asm volatile("cp.async.cg.shared.global [%0], [%1], 16;"
            :: "r"(ad), "l"(asrc));
        asm volatile("cp.async.cg.shared.global [%0], [%1], 16;"
            :: "r"(ad + 16), "l"(asrc + 8));
        const __half* bsrc = wbase + (tap*CHAN + cq*64)*CHAN;
        uint32_t bd = bdst0 + st*STAGE_B;
        #pragma unroll
        for (int j = 0; j < 4; j++)
            asm volatile("cp.async.cg.shared.global [%0], [%1], 16;"
                :: "r"(bd + (uint32_t)(j*16*BST)*2), "l"(bsrc + j*16*CHAN));
        asm volatile("cp.async.commit_group;");
    };

    fill(0); fill(1);

    for (int c = 0; c < NCHUNK; c++) {
        asm volatile("cp.async.wait_group %0;" :: "n"(1));
        __syncthreads();
        if (c + 2 < NCHUNK) fill(c + 2);
        else asm volatile("cp.async.commit_group;");

        int st = c % STAGES;
        const __half* Ab = (const __half*)(smem + st*STAGE_B);
        const __half* Bb = (const __half*)(smem + st*STAGE_B + A_BYTES);

        #pragma unroll
        for (int kk = 0; kk < 4; kk++) {
            uint32_t afr[4][4];
            uint32_t bfr[4][2];
            #pragma unroll
            for (int mf = 0; mf < 4; mf++) {
                int row = wm*64 + mf*16 + (lane & 15);
                int col = kk*16 + ((lane >> 4) << 3);
                uint32_t addr = smem_u32(&Ab[row*AST + col]);
                asm volatile("ldmatrix.sync.aligned.m8n8.x4.shared.b16 {%0,%1,%2,%3},[%4];"
                    : "=r"(afr[mf][0]), "=r"(afr[mf][1]), "=r"(afr[mf][2]), "=r"(afr[mf][3])
                    : "r"(addr));
            }
            #pragma unroll
            for (int bg = 0; bg < 2; bg++) {
                int row = kk*16 + (lane & 15);
                int col = wn*32 + bg*16 + ((lane >> 4) << 3);
                uint32_t addr = smem_u32(&Bb[row*BST + col]);
                asm volatile("ldmatrix.sync.aligned.m8n8.x4.trans.shared.b16 {%0,%1,%2,%3},[%4];"
                    : "=r"(bfr[bg*2][0]), "=r"(bfr[bg*2][1]),
                      "=r"(bfr[bg*2+1][0]), "=r"(bfr[bg*2+1][1])
                    : "r"(addr));
            }
            #pragma unroll
            for (int mf = 0; mf < 4; mf++)
                #pragma unroll
                for (int nf = 0; nf < 4; nf++)
                    asm volatile(
                        "mma.sync.aligned.m16n8k16.row.col.f32.f16.f16.f32 "
                        "{%0,%1,%2,%3},{%4,%5,%6,%7},{%8,%9},{%0,%1,%2,%3};"
                        : "+f"(acc[mf][nf][0]), "+f"(acc[mf][nf][1]),
                          "+f"(acc[mf][nf][2]), "+f"(acc[mf][nf][3])
                        : "r"(afr[mf][0]), "r"(afr[mf][1]), "r"(afr[mf][2]), "r"(afr[mf][3]),
                          "r"(bfr[nf][0]), "r"(bfr[nf][1]));
        }
    }

    // ---- epilogue: BN + PACT quantization ----
    float aval = alpha_p[0];
    float back = __fdiv_rn(aval, 15.0f);
    #pragma unroll
    for (int mf = 0; mf < 4; mf++) {
        #pragma unroll
        for (int jh = 0; jh < 2; jh++) {
            int rm  = m0 + wm*64 + mf*16 + (lane >> 2) + jh*8;
            int b2  = rm / HWHW;
            int hw2 = rm - b2*HWHW;
            float* obase = out + b2*CHAN*HWHW + hw2;
            #pragma unroll
            for (int nf = 0; nf < 4; nf++) {
                #pragma unroll
                for (int jl = 0; jl < 2; jl++) {
                    int j  = jh*2 + jl;
                    int oc = wn*32 + nf*8 + ((lane & 3) << 1) + jl;
                    float y = fmaf(acc[mf][nf][j], s_scale[oc], s_bias[oc]);
                    y = fminf(fmaxf(y, 0.0f), aval);
                    float q = rintf(__fdiv_rn(y * 15.0f, aval)) * back;
                    obase[oc * HWHW] = q;
                }
            }
        }
    }
}

// ---------------- launch ----------------------------------------------------
extern "C" void kernel_launch(void* const* d_in, const int* in_sizes, int n_in,
                              void* d_out, int out_size) {
    const float* x     = (const float*)d_in[0];
    const float* w     = (const float*)d_in[1];
    const float* gamma = (const float*)d_in[2];
    const float* beta  = (const float*)d_in[3];
    const float* mean  = (const float*)d_in[4];
    const float* var   = (const float*)d_in[5];
    const float* alpha = (const float*)d_in[6];
    float* out = (float*)d_out;

    static int init_done = 0;
    static void* tbits_ptr = 0;
    if (!init_done) {
        cudaFuncSetAttribute(k_conv, cudaFuncAttributeMaxDynamicSharedMemorySize, SMEM_REQ);
        cudaGetSymbolAddress(&tbits_ptr, g_Tbits);
        init_done = 1;
    }

    cudaMemsetAsync(tbits_ptr, 0, 4);          // re-zero the atomic-max cell
    k_max<<<256, 256>>>(w);
    k_prep_w<<<KDIM, 256>>>(w, gamma, beta, mean, var);
    k_convert<<<BATCH*HH*2, 128>>>(x);
    k_conv<<<MDIM/BM, 512, SMEM_REQ>>>(alpha, out);
}